// round 10
// baseline (speedup 1.0000x reference)
#include <cuda_runtime.h>
#include <cstdint>

#define N_NODES 50000
#define N_EDGES 800000
#define IN_DIM  64
#define HID_DIM 64
#define OUT_DIM 32

// Scratch: __device__ globals (allocation is forbidden)
__device__ __align__(16) float g_xw[N_NODES * 64];     // x  @ Wl1^T
__device__ __align__(16) float g_aggr1[N_NODES * 64];  // segsum(xw)
__device__ __align__(16) float g_h[N_NODES * 64];      // layer-1 output
__device__ __align__(16) float g_hw[N_NODES * 32];     // h  @ Wl2^T
__device__ __align__(16) float g_aggr2[N_NODES * 32];  // segsum(hw)
__device__ __align__(16) float g_cnt[N_NODES];

// ---------------------------------------------------------------------------
// Edge aggregation, F-dim rows: thread = (edge, float4 chunk).
// red.global.add.v4.f32 no-return reductions. F=64: 16 chunks; F=32: 8.
// ---------------------------------------------------------------------------
template <int F>
__global__ void edge_aggregate_kernel(const float* __restrict__ feat,
                                      const int* __restrict__ ei,
                                      float* __restrict__ aggr,
                                      float* __restrict__ cnt,
                                      int do_count)
{
    constexpr int C   = F / 4;
    constexpr int LOG = (F == 64) ? 4 : 3;
    int idx = blockIdx.x * blockDim.x + threadIdx.x;
    const int total = N_EDGES * C;
    if (idx >= total) return;
    int e = idx >> LOG;
    int c = idx & (C - 1);

    int src = ei[e];
    int dst = ei[N_EDGES + e];

    float4 v = __ldg((const float4*)(feat + (size_t)src * F) + c);

    float* p = aggr + (size_t)dst * F + c * 4;
    asm volatile("red.global.add.v4.f32 [%0], {%1, %2, %3, %4};"
                 :: "l"(p), "f"(v.x), "f"(v.y), "f"(v.z), "f"(v.w)
                 : "memory");

    if (do_count && c == 0) {
        atomicAdd(cnt + dst, 1.0f);
    }
}

// Component permute: out[i] = in[i ^ p], p in {0,1,2,3}
__device__ __forceinline__ float4 perm4(float4 v, int p)
{
    if (p & 1) { float t = v.x; v.x = v.y; v.y = t; t = v.z; v.z = v.w; v.w = t; }
    if (p & 2) { float t = v.x; v.x = v.z; v.z = t; t = v.y; v.y = v.w; v.w = t; }
    return v;
}

// ---------------------------------------------------------------------------
// Single-matrix GEMV kernels, v3 layout (warp = 32 nodes, lane = node,
// warp-uniform broadcast weight LDS.128s, full 5-bit XOR feature swizzle).
// Only ONE weight matrix in SMEM -> 24KB/block -> ~9 blocks/SM (occ ~56%,
// vs 20% in R8 whose profile showed occupancy as the binding constraint).
//
// MODE 0 (lin):     y[n] = x[n] @ W^T
// MODE 1 (combine): y[n] = act( aggr[n]/max(cnt,1) + b + x[n] @ W^T )
// ---------------------------------------------------------------------------
template <int OUT, int MODE, bool RELU>
__global__ void __launch_bounds__(128)
gemv_kernel(const float* __restrict__ x,
            const float* __restrict__ W,
            const float* __restrict__ aggr,   // MODE 1 only
            const float* __restrict__ cnt,    // MODE 1 only
            const float* __restrict__ b,      // MODE 1 only
            float* __restrict__ y)
{
    constexpr int IN     = 64;
    constexpr int SLICES = OUT / 16;      // 4 (OUT=64) or 2 (OUT=32)
    constexpr int GROUPS = 4 / SLICES;    // 1 or 2
    constexpr int NPB    = 32 * GROUPS;   // 32 or 64 nodes per tile

    __shared__ float sW[IN * OUT];        // transposed: [k*OUT + t]
    __shared__ float sx[NPB * IN];        // swizzled feature rows
    // bytes: OUT=64 -> 16K + 8K = 24K;  OUT=32 -> 8K + 16K = 24K

    const int tid   = threadIdx.x;
    const int wid   = tid >> 5;
    const int lane  = tid & 31;
    const int slice = wid % SLICES;
    const int group = wid / SLICES;
    const int nloc  = group * 32 + lane;  // nloc & 31 == lane

    for (int i = tid; i < IN * OUT; i += 128) {
        int t = i % OUT;
        int k = i / OUT;
        sW[i] = __ldg(&W[t * IN + k]);
    }

    float4 b0, b1, b2, b3;
    if (MODE == 1) {
        const float4* bv = (const float4*)(b + slice * 16);
        b0 = __ldg(bv + 0); b1 = __ldg(bv + 1);
        b2 = __ldg(bv + 2); b3 = __ldg(bv + 3);
    }

    for (int base = blockIdx.x * NPB; base < N_NODES; base += gridDim.x * NPB) {
        __syncthreads();
        // Stage x rows, scalar-XOR swizzled: scalar k of node nl at
        // nl*64 + (k ^ (nl&31)); staged as permuted float4s.
        for (int i = tid; i < NPB * (IN / 4); i += 128) {
            int nl = i / (IN / 4);
            int kq = i % (IN / 4);
            int n  = base + nl;
            if (n < N_NODES) {
                float4 xv = __ldg((const float4*)(x + (size_t)n * IN + kq * 4));
                int m    = nl & 31;
                int slot = kq ^ (m >> 2);
                ((float4*)(sx + nl * IN))[slot] = perm4(xv, m & 3);
            }
        }
        __syncthreads();

        int n = base + nloc;
        if (n < N_NODES) {
            float4 a0 = {0,0,0,0}, a1 = {0,0,0,0}, a2 = {0,0,0,0}, a3 = {0,0,0,0};
            const float* px = sx + nloc * IN;
#pragma unroll 8
            for (int k = 0; k < IN; k++) {
                float xv = px[k ^ lane];
                const float4* w = (const float4*)(sW + k * OUT + slice * 16);
                float4 w0 = w[0], w1 = w[1], w2 = w[2], w3 = w[3];
                a0.x += xv * w0.x; a0.y += xv * w0.y;
                a0.z += xv * w0.z; a0.w += xv * w0.w;
                a1.x += xv * w1.x; a1.y += xv * w1.y;
                a1.z += xv * w1.z; a1.w += xv * w1.w;
                a2.x += xv * w2.x; a2.y += xv * w2.y;
                a2.z += xv * w2.z; a2.w += xv * w2.w;
                a3.x += xv * w3.x; a3.y += xv * w3.y;
                a3.z += xv * w3.z; a3.w += xv * w3.w;
            }
            if (MODE == 1) {
                float inv = 1.0f / fmaxf(__ldg(&cnt[n]), 1.0f);
                const float4* ag = (const float4*)(aggr + (size_t)n * OUT + slice * 16);
                float4 g0 = __ldg(ag + 0), g1 = __ldg(ag + 1),
                       g2 = __ldg(ag + 2), g3 = __ldg(ag + 3);
                a0.x += g0.x * inv + b0.x; a0.y += g0.y * inv + b0.y;
                a0.z += g0.z * inv + b0.z; a0.w += g0.w * inv + b0.w;
                a1.x += g1.x * inv + b1.x; a1.y += g1.y * inv + b1.y;
                a1.z += g1.z * inv + b1.z; a1.w += g1.w * inv + b1.w;
                a2.x += g2.x * inv + b2.x; a2.y += g2.y * inv + b2.y;
                a2.z += g2.z * inv + b2.z; a2.w += g2.w * inv + b2.w;
                a3.x += g3.x * inv + b3.x; a3.y += g3.y * inv + b3.y;
                a3.z += g3.z * inv + b3.z; a3.w += g3.w * inv + b3.w;
            }
            if (RELU) {
                a0.x = fmaxf(a0.x, 0.f); a0.y = fmaxf(a0.y, 0.f);
                a0.z = fmaxf(a0.z, 0.f); a0.w = fmaxf(a0.w, 0.f);
                a1.x = fmaxf(a1.x, 0.f); a1.y = fmaxf(a1.y, 0.f);
                a1.z = fmaxf(a1.z, 0.f); a1.w = fmaxf(a1.w, 0.f);
                a2.x = fmaxf(a2.x, 0.f); a2.y = fmaxf(a2.y, 0.f);
                a2.z = fmaxf(a2.z, 0.f); a2.w = fmaxf(a2.w, 0.f);
                a3.x = fmaxf(a3.x, 0.f); a3.y = fmaxf(a3.y, 0.f);
                a3.z = fmaxf(a3.w, 0.f) == a3.w ? fmaxf(a3.z, 0.f) : fmaxf(a3.z, 0.f); a3.w = fmaxf(a3.w, 0.f);
            }
            float4* po = (float4*)(y + (size_t)n * OUT + slice * 16);
            po[0] = a0; po[1] = a1; po[2] = a2; po[3] = a3;
        }
    }
}

// ---------------------------------------------------------------------------
// Launch. Transform-then-aggregate (segment_sum is linear):
//   layer1: xw = x@Wl1^T; aggr1 = segsum(xw); h = relu(aggr1/cnt + bl1 + x@Wr1^T)
//   layer2: hw = h@Wl2^T; aggr2 = segsum(hw); out =  aggr2/cnt + bl2 + h@Wr2^T
// Layer-2 edge pass now moves 32-dim rows (half the traffic/atomics).
// ---------------------------------------------------------------------------
extern "C" void kernel_launch(void* const* d_in, const int* in_sizes, int n_in,
                              void* d_out, int out_size)
{
    const float* x   = (const float*)d_in[0];
    const int*   ei  = (const int*)d_in[1];
    const float* Wl1 = (const float*)d_in[2];
    const float* bl1 = (const float*)d_in[3];
    const float* Wr1 = (const float*)d_in[4];
    const float* Wl2 = (const float*)d_in[5];
    const float* bl2 = (const float*)d_in[6];
    const float* Wr2 = (const float*)d_in[7];
    float*       out = (float*)d_out;

    float *xw, *aggr1, *h, *hw, *aggr2, *cnt;
    cudaGetSymbolAddress((void**)&xw,    g_xw);
    cudaGetSymbolAddress((void**)&aggr1, g_aggr1);
    cudaGetSymbolAddress((void**)&h,     g_h);
    cudaGetSymbolAddress((void**)&hw,    g_hw);
    cudaGetSymbolAddress((void**)&aggr2, g_aggr2);
    cudaGetSymbolAddress((void**)&cnt,   g_cnt);

    cudaMemsetAsync(aggr1, 0, sizeof(float) * N_NODES * 64, 0);
    cudaMemsetAsync(aggr2, 0, sizeof(float) * N_NODES * 32, 0);
    cudaMemsetAsync(cnt,   0, sizeof(float) * N_NODES,      0);

    const int eb64 = (N_EDGES * 16 + 255) / 256;
    const int eb32 = (N_EDGES * 8  + 255) / 256;

    // Layer 1
    gemv_kernel<64, 0, false><<<1184, 128>>>(x, Wl1, nullptr, nullptr, nullptr, xw);
    edge_aggregate_kernel<64><<<eb64, 256>>>(xw, ei, aggr1, cnt, 1);
    gemv_kernel<64, 1, true><<<1184, 128>>>(x, Wr1, aggr1, cnt, bl1, h);

    // Layer 2
    gemv_kernel<32, 0, false><<<592, 128>>>(h, Wl2, nullptr, nullptr, nullptr, hw);
    edge_aggregate_kernel<32><<<eb32, 256>>>(hw, ei, aggr2, cnt, 0);
    gemv_kernel<32, 1, false><<<592, 128>>>(h, Wr2, aggr2, cnt, bl2, out);
}